// round 1
// baseline (speedup 1.0000x reference)
#include <cuda_runtime.h>
#include <math.h>

// Shapes
#define BB 512
#define TT 512
#define DD 128
#define HH 64

// Scratch (device globals: allocation-free per harness rules)
// pre  : [t][b][j]  (T-major so the scan streams contiguous slabs)
// ball : [t][b][0..4] padded to 8 floats for aligned float4 access
__device__ float g_pre[(size_t)TT * BB * HH];
__device__ float g_ball[(size_t)TT * BB * 8];

// ---------------- packed fp32x2 helpers (Blackwell FFMA2) ----------------
__device__ __forceinline__ unsigned long long fma2(unsigned long long a,
                                                   unsigned long long b,
                                                   unsigned long long c) {
    unsigned long long d;
    asm("fma.rn.f32x2 %0, %1, %2, %3;" : "=l"(d) : "l"(a), "l"(b), "l"(c));
    return d;
}
__device__ __forceinline__ unsigned long long pack2(float lo, float hi) {
    unsigned long long d;
    asm("mov.b64 %0, {%1, %2};" : "=l"(d) : "f"(lo), "f"(hi));
    return d;
}
__device__ __forceinline__ void unpack2(unsigned long long v, float& lo, float& hi) {
    asm("mov.b64 {%0, %1}, %2;" : "=f"(lo), "=f"(hi) : "l"(v));
}

// exact gelu: x * Phi(x)
__device__ __forceinline__ float gelu_exact(float x) { return x * normcdff(x); }

// =====================================================================
// Phase 1: per token: h = gelu(LN(x@W1+b1)); pre = h@Wc1[5:]+bc1;
//          b_all = h@W_inn + b_inn.  One token per thread.
// =====================================================================
__global__ __launch_bounds__(256) void phase1_kernel(
    const float* __restrict__ x, const float* __restrict__ W1,
    const float* __restrict__ b1, const float* __restrict__ ln_g,
    const float* __restrict__ ln_b, const float* __restrict__ W_inn,
    const float* __restrict__ b_inn, const float* __restrict__ Wc1,
    const float* __restrict__ bc1) {
    __shared__ __align__(16) float sW1[DD * HH];    // 32 KB
    __shared__ __align__(16) float sWc1h[HH * HH];  // 16 KB  (total exactly 48 KB)

    const int tid = threadIdx.x;
    for (int i = tid; i < DD * HH; i += 256) sW1[i] = W1[i];
    for (int i = tid; i < HH * HH; i += 256) sWc1h[i] = Wc1[5 * HH + i];
    __syncthreads();

    const int token = blockIdx.x * 256 + tid;  // = b*512 + t
    const int t = token & (TT - 1);
    const int b = token >> 9;

    // ---- GEMM1: acc[jp] covers h columns (2jp, 2jp+1) ----
    unsigned long long acc[32];
#pragma unroll
    for (int q = 0; q < 32; q++) acc[q] = pack2(__ldg(b1 + 2 * q), __ldg(b1 + 2 * q + 1));

    const float4* xr = reinterpret_cast<const float4*>(x + (size_t)token * DD);
#pragma unroll 2
    for (int kc = 0; kc < 32; kc++) {
        float4 xv = __ldg(xr + kc);
        float xs[4] = {xv.x, xv.y, xv.z, xv.w};
#pragma unroll
        for (int kk = 0; kk < 4; kk++) {
            const int k = kc * 4 + kk;
            unsigned long long xd = pack2(xs[kk], xs[kk]);
            const ulonglong2* wr = reinterpret_cast<const ulonglong2*>(sW1 + k * HH);
#pragma unroll
            for (int q2 = 0; q2 < 16; q2++) {
                ulonglong2 w = wr[q2];
                acc[2 * q2]     = fma2(xd, w.x, acc[2 * q2]);
                acc[2 * q2 + 1] = fma2(xd, w.y, acc[2 * q2 + 1]);
            }
        }
    }

    float h[HH];
#pragma unroll
    for (int q = 0; q < 32; q++) unpack2(acc[q], h[2 * q], h[2 * q + 1]);

    // ---- LayerNorm over 64 + exact gelu ----
    float s1 = 0.f, s2 = 0.f;
#pragma unroll
    for (int j = 0; j < HH; j++) { s1 += h[j]; s2 += h[j] * h[j]; }
    const float mean = s1 * (1.0f / HH);
    const float var = s2 * (1.0f / HH) - mean * mean;
    const float rstd = rsqrtf(var + 1e-5f);
#pragma unroll
    for (int j = 0; j < HH; j++) {
        float v = (h[j] - mean) * rstd * __ldg(ln_g + j) + __ldg(ln_b + j);
        h[j] = gelu_exact(v);
    }

    // ---- GEMM2: pre = h @ Wc1_h + bc1 ----
    unsigned long long po[32];
#pragma unroll
    for (int q = 0; q < 32; q++) po[q] = pack2(__ldg(bc1 + 2 * q), __ldg(bc1 + 2 * q + 1));
#pragma unroll 2
    for (int k = 0; k < HH; k++) {
        unsigned long long hd = pack2(h[k], h[k]);
        const ulonglong2* wr = reinterpret_cast<const ulonglong2*>(sWc1h + k * HH);
#pragma unroll
        for (int q2 = 0; q2 < 16; q2++) {
            ulonglong2 w = wr[q2];
            po[2 * q2]     = fma2(hd, w.x, po[2 * q2]);
            po[2 * q2 + 1] = fma2(hd, w.y, po[2 * q2 + 1]);
        }
    }

    // ---- b_all = h @ W_inn + b_inn ----
    float bb[5];
#pragma unroll
    for (int s = 0; s < 5; s++) bb[s] = __ldg(b_inn + s);
#pragma unroll 4
    for (int k = 0; k < HH; k++) {
        float hk = h[k];
#pragma unroll
        for (int s = 0; s < 5; s++) bb[s] = fmaf(hk, __ldg(W_inn + k * 5 + s), bb[s]);
    }

    // ---- writes (T-major scratch) ----
    float* pd = g_pre + ((size_t)t * BB + b) * HH;
#pragma unroll
    for (int q2 = 0; q2 < 16; q2++) {
        float l0, h0, l1, h1;
        unpack2(po[2 * q2], l0, h0);
        unpack2(po[2 * q2 + 1], l1, h1);
        reinterpret_cast<float4*>(pd)[q2] = make_float4(l0, h0, l1, h1);
    }
    float* bd = g_ball + ((size_t)t * BB + b) * 8;
    reinterpret_cast<float4*>(bd)[0] = make_float4(bb[0], bb[1], bb[2], bb[3]);
    bd[4] = bb[4];
}

// =====================================================================
// Phase 2: sequential scan. 8 lanes per batch row (4 rows/warp),
// one warp per CTA, 128 CTAs -> 1 warp/SM (dedicated issue slots).
// Depth-4 register prefetch hides DRAM/L2 latency.
// =====================================================================
__device__ __forceinline__ float sigmoidf_(float v) { return 1.0f / (1.0f + expf(-v)); }

__global__ __launch_bounds__(32) void scan_kernel(
    const float* __restrict__ Wc1, const float* __restrict__ Wc2,
    const float* __restrict__ bc2, const float* __restrict__ corr_scale,
    const float* __restrict__ raw_aL, const float* __restrict__ raw_aT,
    const float* __restrict__ raw_g, const float* __restrict__ raw_aR,
    const float* __restrict__ omega, float* __restrict__ out) {
    const int lane = threadIdx.x;
    const int sub = lane & 7;            // lane within row-group
    const int row = blockIdx.x * 4 + (lane >> 3);
    const int j0 = sub * 8;

    // per-lane weight slices (registers)
    float w1s[5][8], w2[8][5], bc[5];
#pragma unroll
    for (int k = 0; k < 5; k++)
#pragma unroll
        for (int jj = 0; jj < 8; jj++) w1s[k][jj] = __ldg(&Wc1[k * 64 + j0 + jj]);
#pragma unroll
    for (int jj = 0; jj < 8; jj++)
#pragma unroll
        for (int k = 0; k < 5; k++) w2[jj][k] = __ldg(&Wc2[(j0 + jj) * 5 + k]);
#pragma unroll
    for (int k = 0; k < 5; k++) bc[k] = __ldg(bc2 + k);

    const float aL = sigmoidf_(__ldg(raw_aL)) * 0.15f + 0.85f;
    const float aT = sigmoidf_(__ldg(raw_aT)) * 0.25f + 0.70f;
    const float gg = sigmoidf_(__ldg(raw_g)) * 0.20f + 0.80f;
    const float aR = sigmoidf_(__ldg(raw_aR)) * 0.40f;
    const float om = __ldg(omega);
    const float gc = gg * cosf(om), gs = gg * sinf(om);
    const float cs = __ldg(corr_scale);

    float s0 = 0.f, s1 = 0.f, s2v = 0.f, s3 = 0.f, s4 = 0.f;

    float pb[4][8];
    float bb[4][5];

    // prologue prefetch t = 0..3
#pragma unroll
    for (int u = 0; u < 4; u++) {
        const float* pp = g_pre + ((size_t)u * BB + row) * HH + j0;
        float4 a0 = __ldg(reinterpret_cast<const float4*>(pp));
        float4 a1 = __ldg(reinterpret_cast<const float4*>(pp) + 1);
        pb[u][0] = a0.x; pb[u][1] = a0.y; pb[u][2] = a0.z; pb[u][3] = a0.w;
        pb[u][4] = a1.x; pb[u][5] = a1.y; pb[u][6] = a1.z; pb[u][7] = a1.w;
        const float* bp = g_ball + ((size_t)u * BB + row) * 8;
        float4 c = __ldg(reinterpret_cast<const float4*>(bp));
        bb[u][0] = c.x; bb[u][1] = c.y; bb[u][2] = c.z; bb[u][3] = c.w;
        bb[u][4] = __ldg(bp + 4);
    }

    for (int tb = 0; tb < TT; tb += 4) {
#pragma unroll
        for (int u = 0; u < 4; u++) {
            const int t = tb + u;
            // s_lin = gate(s) + b_t
            float sl0 = fmaf(s0, aL, bb[u][0]);
            float sl1 = fmaf(s1, aT, bb[u][1]);
            float sl2 = fmaf(s2v, gc, fmaf(s3, gs, bb[u][2]));
            float sl3 = fmaf(s3, gc, fmaf(-s2v, gs, bb[u][3]));
            float sl4 = fmaf(s4, aR, bb[u][4]);

            float p0 = 0.f, p1 = 0.f, p2 = 0.f, p3 = 0.f, p4 = 0.f;
#pragma unroll
            for (int jj = 0; jj < 8; jj++) {
                float z = pb[u][jj];
                z = fmaf(sl0, w1s[0][jj], z);
                z = fmaf(sl1, w1s[1][jj], z);
                z = fmaf(sl2, w1s[2][jj], z);
                z = fmaf(sl3, w1s[3][jj], z);
                z = fmaf(sl4, w1s[4][jj], z);
                float hg = gelu_exact(z);
                p0 = fmaf(hg, w2[jj][0], p0);
                p1 = fmaf(hg, w2[jj][1], p1);
                p2 = fmaf(hg, w2[jj][2], p2);
                p3 = fmaf(hg, w2[jj][3], p3);
                p4 = fmaf(hg, w2[jj][4], p4);
            }

            // prefetch t+4 into this slot (data just consumed)
            if (t + 4 < TT) {
                const float* pp = g_pre + ((size_t)(t + 4) * BB + row) * HH + j0;
                float4 a0 = __ldg(reinterpret_cast<const float4*>(pp));
                float4 a1 = __ldg(reinterpret_cast<const float4*>(pp) + 1);
                pb[u][0] = a0.x; pb[u][1] = a0.y; pb[u][2] = a0.z; pb[u][3] = a0.w;
                pb[u][4] = a1.x; pb[u][5] = a1.y; pb[u][6] = a1.z; pb[u][7] = a1.w;
                const float* bp = g_ball + ((size_t)(t + 4) * BB + row) * 8;
                float4 c = __ldg(reinterpret_cast<const float4*>(bp));
                bb[u][0] = c.x; bb[u][1] = c.y; bb[u][2] = c.z; bb[u][3] = c.w;
                bb[u][4] = __ldg(bp + 4);
            }

            // butterfly reduce across the 8 lanes of this row
#pragma unroll
            for (int m = 4; m >= 1; m >>= 1) {
                p0 += __shfl_xor_sync(0xffffffffu, p0, m);
                p1 += __shfl_xor_sync(0xffffffffu, p1, m);
                p2 += __shfl_xor_sync(0xffffffffu, p2, m);
                p3 += __shfl_xor_sync(0xffffffffu, p3, m);
                p4 += __shfl_xor_sync(0xffffffffu, p4, m);
            }

            s0 = fmaf(cs, tanhf(p0 + bc[0]), sl0);
            s1 = fmaf(cs, tanhf(p1 + bc[1]), sl1);
            s2v = fmaf(cs, tanhf(p2 + bc[2]), sl2);
            s3 = fmaf(cs, tanhf(p3 + bc[3]), sl3);
            s4 = fmaf(cs, tanhf(p4 + bc[4]), sl4);
        }
    }

    if (sub == 0) {
        out[row * 5 + 0] = s0;
        out[row * 5 + 1] = s1;
        out[row * 5 + 2] = s2v;
        out[row * 5 + 3] = s3;
        out[row * 5 + 4] = s4;
    }
}

// =====================================================================
extern "C" void kernel_launch(void* const* d_in, const int* in_sizes, int n_in,
                              void* d_out, int out_size) {
    const float* x = (const float*)d_in[0];
    const float* W1 = (const float*)d_in[1];
    const float* b1 = (const float*)d_in[2];
    const float* ln_g = (const float*)d_in[3];
    const float* ln_b = (const float*)d_in[4];
    const float* W_inn = (const float*)d_in[5];
    const float* b_inn = (const float*)d_in[6];
    const float* Wc1 = (const float*)d_in[7];
    const float* bc1 = (const float*)d_in[8];
    const float* Wc2 = (const float*)d_in[9];
    const float* bc2 = (const float*)d_in[10];
    const float* corr_scale = (const float*)d_in[11];
    const float* raw_aL = (const float*)d_in[12];
    const float* raw_aT = (const float*)d_in[13];
    const float* raw_g = (const float*)d_in[14];
    const float* raw_aR = (const float*)d_in[15];
    const float* omega = (const float*)d_in[16];
    float* out = (float*)d_out;

    phase1_kernel<<<(BB * TT) / 256, 256>>>(x, W1, b1, ln_g, ln_b, W_inn, b_inn, Wc1, bc1);
    scan_kernel<<<BB / 4, 32>>>(Wc1, Wc2, bc2, corr_scale, raw_aL, raw_aT, raw_g,
                                raw_aR, omega, out);
}

// round 2
// speedup vs baseline: 1.9943x; 1.9943x over previous
#include <cuda_runtime.h>
#include <math.h>

// Shapes
#define BB 512
#define TT 512
#define DD 128
#define HH 64

// Scratch (device globals: allocation-free per harness rules)
// pre  : [t][b][j]  (T-major so the scan streams contiguous slabs)
// ball : [t][b][0..4] padded to 8 floats for aligned float4 access
__device__ float g_pre[(size_t)TT * BB * HH];
__device__ float g_ball[(size_t)TT * BB * 8];

// ---------------- packed fp32x2 helpers (Blackwell FFMA2) ----------------
__device__ __forceinline__ unsigned long long fma2(unsigned long long a,
                                                   unsigned long long b,
                                                   unsigned long long c) {
    unsigned long long d;
    asm("fma.rn.f32x2 %0, %1, %2, %3;" : "=l"(d) : "l"(a), "l"(b), "l"(c));
    return d;
}
__device__ __forceinline__ unsigned long long pack2(float lo, float hi) {
    unsigned long long d;
    asm("mov.b64 %0, {%1, %2};" : "=l"(d) : "f"(lo), "f"(hi));
    return d;
}
__device__ __forceinline__ void unpack2(unsigned long long v, float& lo, float& hi) {
    asm("mov.b64 {%0, %1}, %2;" : "=f"(lo), "=f"(hi) : "l"(v));
}

// ---------------- fast transcendentals (HW MUFU tanh) ----------------
__device__ __forceinline__ float tanh_fast(float x) {
    float y;
    asm("tanh.approx.f32 %0, %1;" : "=f"(y) : "f"(x));
    return y;
}
// tanh-form gelu: 0.5*x*(1+tanh(x*(0.7978845608 + 0.0356774081*x^2)))
__device__ __forceinline__ float gelu_fast(float x) {
    float x2 = x * x;
    float u = x * fmaf(x2, 0.0356774081f, 0.7978845608f);
    float t = tanh_fast(u);
    return x * fmaf(t, 0.5f, 0.5f);
}

// =====================================================================
// Phase 1: per token: h = gelu(LN(x@W1+b1)); pre = h@Wc1[5:]+bc1;
//          b_all = h@W_inn + b_inn.  One token per thread.
// =====================================================================
__global__ __launch_bounds__(256) void phase1_kernel(
    const float* __restrict__ x, const float* __restrict__ W1,
    const float* __restrict__ b1, const float* __restrict__ ln_g,
    const float* __restrict__ ln_b, const float* __restrict__ W_inn,
    const float* __restrict__ b_inn, const float* __restrict__ Wc1,
    const float* __restrict__ bc1) {
    __shared__ __align__(16) float sW1[DD * HH];    // 32 KB
    __shared__ __align__(16) float sWc1h[HH * HH];  // 16 KB  (total exactly 48 KB)

    const int tid = threadIdx.x;
    for (int i = tid; i < DD * HH; i += 256) sW1[i] = W1[i];
    for (int i = tid; i < HH * HH; i += 256) sWc1h[i] = Wc1[5 * HH + i];
    __syncthreads();

    const int token = blockIdx.x * 256 + tid;  // = b*512 + t
    const int t = token & (TT - 1);
    const int b = token >> 9;

    // ---- GEMM1: acc[jp] covers h columns (2jp, 2jp+1) ----
    unsigned long long acc[32];
#pragma unroll
    for (int q = 0; q < 32; q++) acc[q] = pack2(__ldg(b1 + 2 * q), __ldg(b1 + 2 * q + 1));

    const float4* xr = reinterpret_cast<const float4*>(x + (size_t)token * DD);
#pragma unroll 2
    for (int kc = 0; kc < 32; kc++) {
        float4 xv = __ldg(xr + kc);
        float xs[4] = {xv.x, xv.y, xv.z, xv.w};
#pragma unroll
        for (int kk = 0; kk < 4; kk++) {
            const int k = kc * 4 + kk;
            unsigned long long xd = pack2(xs[kk], xs[kk]);
            const ulonglong2* wr = reinterpret_cast<const ulonglong2*>(sW1 + k * HH);
#pragma unroll
            for (int q2 = 0; q2 < 16; q2++) {
                ulonglong2 w = wr[q2];
                acc[2 * q2]     = fma2(xd, w.x, acc[2 * q2]);
                acc[2 * q2 + 1] = fma2(xd, w.y, acc[2 * q2 + 1]);
            }
        }
    }

    float h[HH];
#pragma unroll
    for (int q = 0; q < 32; q++) unpack2(acc[q], h[2 * q], h[2 * q + 1]);

    // ---- LayerNorm over 64 + fast gelu ----
    float s1 = 0.f, s2 = 0.f;
#pragma unroll
    for (int j = 0; j < HH; j++) { s1 += h[j]; s2 += h[j] * h[j]; }
    const float mean = s1 * (1.0f / HH);
    const float var = s2 * (1.0f / HH) - mean * mean;
    const float rstd = rsqrtf(var + 1e-5f);
#pragma unroll
    for (int j = 0; j < HH; j++) {
        float v = (h[j] - mean) * rstd * __ldg(ln_g + j) + __ldg(ln_b + j);
        h[j] = gelu_fast(v);
    }

    // ---- GEMM2: pre = h @ Wc1_h + bc1 ----
    unsigned long long po[32];
#pragma unroll
    for (int q = 0; q < 32; q++) po[q] = pack2(__ldg(bc1 + 2 * q), __ldg(bc1 + 2 * q + 1));
#pragma unroll 2
    for (int k = 0; k < HH; k++) {
        unsigned long long hd = pack2(h[k], h[k]);
        const ulonglong2* wr = reinterpret_cast<const ulonglong2*>(sWc1h + k * HH);
#pragma unroll
        for (int q2 = 0; q2 < 16; q2++) {
            ulonglong2 w = wr[q2];
            po[2 * q2]     = fma2(hd, w.x, po[2 * q2]);
            po[2 * q2 + 1] = fma2(hd, w.y, po[2 * q2 + 1]);
        }
    }

    // ---- b_all = h @ W_inn + b_inn ----
    float bb[5];
#pragma unroll
    for (int s = 0; s < 5; s++) bb[s] = __ldg(b_inn + s);
#pragma unroll 4
    for (int k = 0; k < HH; k++) {
        float hk = h[k];
#pragma unroll
        for (int s = 0; s < 5; s++) bb[s] = fmaf(hk, __ldg(W_inn + k * 5 + s), bb[s]);
    }

    // ---- writes (T-major scratch) ----
    float* pd = g_pre + ((size_t)t * BB + b) * HH;
#pragma unroll
    for (int q2 = 0; q2 < 16; q2++) {
        float l0, h0, l1, h1;
        unpack2(po[2 * q2], l0, h0);
        unpack2(po[2 * q2 + 1], l1, h1);
        reinterpret_cast<float4*>(pd)[q2] = make_float4(l0, h0, l1, h1);
    }
    float* bd = g_ball + ((size_t)t * BB + b) * 8;
    reinterpret_cast<float4*>(bd)[0] = make_float4(bb[0], bb[1], bb[2], bb[3]);
    bd[4] = bb[4];
}

// =====================================================================
// Phase 2: sequential scan. 8 lanes per batch row (4 rows/warp),
// one warp per CTA, 128 CTAs -> ~1 warp/SM (dedicated issue slots).
// Depth-4 register prefetch hides DRAM/L2 latency.
// =====================================================================
__device__ __forceinline__ float sigmoidf_(float v) { return 1.0f / (1.0f + expf(-v)); }

__global__ __launch_bounds__(32) void scan_kernel(
    const float* __restrict__ Wc1, const float* __restrict__ Wc2,
    const float* __restrict__ bc2, const float* __restrict__ corr_scale,
    const float* __restrict__ raw_aL, const float* __restrict__ raw_aT,
    const float* __restrict__ raw_g, const float* __restrict__ raw_aR,
    const float* __restrict__ omega, float* __restrict__ out) {
    const int lane = threadIdx.x;
    const int sub = lane & 7;            // lane within row-group
    const int row = blockIdx.x * 4 + (lane >> 3);
    const int j0 = sub * 8;

    // per-lane weight slices (registers)
    float w1s[5][8], w2[8][5], bc[5];
#pragma unroll
    for (int k = 0; k < 5; k++)
#pragma unroll
        for (int jj = 0; jj < 8; jj++) w1s[k][jj] = __ldg(&Wc1[k * 64 + j0 + jj]);
#pragma unroll
    for (int jj = 0; jj < 8; jj++)
#pragma unroll
        for (int k = 0; k < 5; k++) w2[jj][k] = __ldg(&Wc2[(j0 + jj) * 5 + k]);
#pragma unroll
    for (int k = 0; k < 5; k++) bc[k] = __ldg(bc2 + k);

    const float aL = sigmoidf_(__ldg(raw_aL)) * 0.15f + 0.85f;
    const float aT = sigmoidf_(__ldg(raw_aT)) * 0.25f + 0.70f;
    const float gg = sigmoidf_(__ldg(raw_g)) * 0.20f + 0.80f;
    const float aR = sigmoidf_(__ldg(raw_aR)) * 0.40f;
    const float om = __ldg(omega);
    const float gc = gg * cosf(om), gs = gg * sinf(om);
    const float cs = __ldg(corr_scale);

    float s0 = 0.f, s1 = 0.f, s2v = 0.f, s3 = 0.f, s4 = 0.f;

    float pb[4][8];
    float bb[4][5];

    // prologue prefetch t = 0..3
#pragma unroll
    for (int u = 0; u < 4; u++) {
        const float* pp = g_pre + ((size_t)u * BB + row) * HH + j0;
        float4 a0 = __ldg(reinterpret_cast<const float4*>(pp));
        float4 a1 = __ldg(reinterpret_cast<const float4*>(pp) + 1);
        pb[u][0] = a0.x; pb[u][1] = a0.y; pb[u][2] = a0.z; pb[u][3] = a0.w;
        pb[u][4] = a1.x; pb[u][5] = a1.y; pb[u][6] = a1.z; pb[u][7] = a1.w;
        const float* bp = g_ball + ((size_t)u * BB + row) * 8;
        float4 c = __ldg(reinterpret_cast<const float4*>(bp));
        bb[u][0] = c.x; bb[u][1] = c.y; bb[u][2] = c.z; bb[u][3] = c.w;
        bb[u][4] = __ldg(bp + 4);
    }

    for (int tb = 0; tb < TT; tb += 4) {
#pragma unroll
        for (int u = 0; u < 4; u++) {
            const int t = tb + u;
            // s_lin = gate(s) + b_t
            float sl0 = fmaf(s0, aL, bb[u][0]);
            float sl1 = fmaf(s1, aT, bb[u][1]);
            float sl2 = fmaf(s2v, gc, fmaf(s3, gs, bb[u][2]));
            float sl3 = fmaf(s3, gc, fmaf(-s2v, gs, bb[u][3]));
            float sl4 = fmaf(s4, aR, bb[u][4]);

            // hmlp = gelu(sl @ Wc1_s + pre); p = hmlp @ Wc2  (split accumulators)
            float pa0 = 0.f, pa1 = 0.f, pa2 = 0.f, pa3 = 0.f, pa4 = 0.f;
            float qb0 = 0.f, qb1 = 0.f, qb2 = 0.f, qb3 = 0.f, qb4 = 0.f;
#pragma unroll
            for (int jj = 0; jj < 8; jj++) {
                float z = pb[u][jj];
                z = fmaf(sl0, w1s[0][jj], z);
                z = fmaf(sl1, w1s[1][jj], z);
                z = fmaf(sl2, w1s[2][jj], z);
                z = fmaf(sl3, w1s[3][jj], z);
                z = fmaf(sl4, w1s[4][jj], z);
                float hg = gelu_fast(z);
                if (jj & 1) {
                    qb0 = fmaf(hg, w2[jj][0], qb0);
                    qb1 = fmaf(hg, w2[jj][1], qb1);
                    qb2 = fmaf(hg, w2[jj][2], qb2);
                    qb3 = fmaf(hg, w2[jj][3], qb3);
                    qb4 = fmaf(hg, w2[jj][4], qb4);
                } else {
                    pa0 = fmaf(hg, w2[jj][0], pa0);
                    pa1 = fmaf(hg, w2[jj][1], pa1);
                    pa2 = fmaf(hg, w2[jj][2], pa2);
                    pa3 = fmaf(hg, w2[jj][3], pa3);
                    pa4 = fmaf(hg, w2[jj][4], pa4);
                }
            }
            float p0 = pa0 + qb0, p1 = pa1 + qb1, p2 = pa2 + qb2,
                  p3 = pa3 + qb3, p4 = pa4 + qb4;

            // prefetch t+4 into this slot (data just consumed)
            if (t + 4 < TT) {
                const float* pp = g_pre + ((size_t)(t + 4) * BB + row) * HH + j0;
                float4 a0 = __ldg(reinterpret_cast<const float4*>(pp));
                float4 a1 = __ldg(reinterpret_cast<const float4*>(pp) + 1);
                pb[u][0] = a0.x; pb[u][1] = a0.y; pb[u][2] = a0.z; pb[u][3] = a0.w;
                pb[u][4] = a1.x; pb[u][5] = a1.y; pb[u][6] = a1.z; pb[u][7] = a1.w;
                const float* bp = g_ball + ((size_t)(t + 4) * BB + row) * 8;
                float4 c = __ldg(reinterpret_cast<const float4*>(bp));
                bb[u][0] = c.x; bb[u][1] = c.y; bb[u][2] = c.z; bb[u][3] = c.w;
                bb[u][4] = __ldg(bp + 4);
            }

            // butterfly reduce across the 8 lanes of this row
#pragma unroll
            for (int m = 4; m >= 1; m >>= 1) {
                p0 += __shfl_xor_sync(0xffffffffu, p0, m);
                p1 += __shfl_xor_sync(0xffffffffu, p1, m);
                p2 += __shfl_xor_sync(0xffffffffu, p2, m);
                p3 += __shfl_xor_sync(0xffffffffu, p3, m);
                p4 += __shfl_xor_sync(0xffffffffu, p4, m);
            }

            s0 = fmaf(cs, tanh_fast(p0 + bc[0]), sl0);
            s1 = fmaf(cs, tanh_fast(p1 + bc[1]), sl1);
            s2v = fmaf(cs, tanh_fast(p2 + bc[2]), sl2);
            s3 = fmaf(cs, tanh_fast(p3 + bc[3]), sl3);
            s4 = fmaf(cs, tanh_fast(p4 + bc[4]), sl4);
        }
    }

    if (sub == 0) {
        out[row * 5 + 0] = s0;
        out[row * 5 + 1] = s1;
        out[row * 5 + 2] = s2v;
        out[row * 5 + 3] = s3;
        out[row * 5 + 4] = s4;
    }
}

// =====================================================================
extern "C" void kernel_launch(void* const* d_in, const int* in_sizes, int n_in,
                              void* d_out, int out_size) {
    const float* x = (const float*)d_in[0];
    const float* W1 = (const float*)d_in[1];
    const float* b1 = (const float*)d_in[2];
    const float* ln_g = (const float*)d_in[3];
    const float* ln_b = (const float*)d_in[4];
    const float* W_inn = (const float*)d_in[5];
    const float* b_inn = (const float*)d_in[6];
    const float* Wc1 = (const float*)d_in[7];
    const float* bc1 = (const float*)d_in[8];
    const float* Wc2 = (const float*)d_in[9];
    const float* bc2 = (const float*)d_in[10];
    const float* corr_scale = (const float*)d_in[11];
    const float* raw_aL = (const float*)d_in[12];
    const float* raw_aT = (const float*)d_in[13];
    const float* raw_g = (const float*)d_in[14];
    const float* raw_aR = (const float*)d_in[15];
    const float* omega = (const float*)d_in[16];
    float* out = (float*)d_out;

    phase1_kernel<<<(BB * TT) / 256, 256>>>(x, W1, b1, ln_g, ln_b, W_inn, b_inn, Wc1, bc1);
    scan_kernel<<<BB / 4, 32>>>(Wc1, Wc2, bc2, corr_scale, raw_aL, raw_aT, raw_g,
                                raw_aR, omega, out);
}